// round 2
// baseline (speedup 1.0000x reference)
#include <cuda_runtime.h>

#define NN 50000
#define EE 800000
#define HH 64
#define CC 10

// Scratch (allocation-free: __device__ globals)
__device__ __align__(16) float g_deg[NN];
__device__ __align__(16) float g_dis[NN];
__device__ __align__(16) float g_h[NN * HH];
__device__ __align__(16) float g_lap[NN * HH];
__device__ int g_stride;  // 1 if edge_index is int32, 2 if int64 (low-word read)

// ---------------------------------------------------------------------------
// Detect edge_index dtype. int64 values in [0,50000) => every odd 32-bit word
// is zero (little-endian). Random int32 indices => essentially impossible.
// ---------------------------------------------------------------------------
__global__ void k_detect(const int* __restrict__ p) {
    int is64 = 1;
#pragma unroll 1
    for (int i = 0; i < 64; i++)
        if (p[2 * i + 1] != 0) { is64 = 0; break; }
    g_stride = is64 ? 2 : 1;
}

// ---------------------------------------------------------------------------
// Zero the per-replay accumulators (lap + deg)
// ---------------------------------------------------------------------------
__global__ __launch_bounds__(256) void k_zero() {
    int i = blockIdx.x * blockDim.x + threadIdx.x;
    const int stride = gridDim.x * blockDim.x;
    const int lap4 = (NN * HH) / 4;
    float4 z = make_float4(0.f, 0.f, 0.f, 0.f);
    for (int j = i; j < lap4; j += stride) ((float4*)g_lap)[j] = z;
    const int deg4 = NN / 4;  // 50000 % 4 == 0
    for (int j = i; j < deg4; j += stride) ((float4*)g_deg)[j] = z;
}

// ---------------------------------------------------------------------------
// Degree: deg[src[e]] += 1
// ---------------------------------------------------------------------------
__global__ __launch_bounds__(256) void k_deg(const int* __restrict__ ei) {
    int e = blockIdx.x * blockDim.x + threadIdx.x;
    if (e < EE) {
        int st = g_stride;
        atomicAdd(&g_deg[ei[e * st]], 1.0f);
    }
}

// ---------------------------------------------------------------------------
// dis[i] = deg>0 ? rsqrt(deg) : 0
// ---------------------------------------------------------------------------
__global__ __launch_bounds__(256) void k_dis() {
    int i = blockIdx.x * blockDim.x + threadIdx.x;
    if (i < NN) {
        float d = g_deg[i];
        g_dis[i] = (d > 0.f) ? rsqrtf(d) : 0.f;
    }
}

// ---------------------------------------------------------------------------
// h = relu(x @ W1 + b1)    (warp per row, W1 in smem)
// ---------------------------------------------------------------------------
__global__ __launch_bounds__(256) void k_gemm1(const float* __restrict__ x,
                                               const float* __restrict__ W1,
                                               const float* __restrict__ b1) {
    __shared__ float Ws[HH * HH];
    __shared__ float xs[8][HH];
    for (int i = threadIdx.x; i < HH * HH; i += 256) Ws[i] = W1[i];
    __syncthreads();

    int warp = threadIdx.x >> 5;
    int lane = threadIdx.x & 31;
    int row = blockIdx.x * 8 + warp;
    if (row >= NN) return;

    xs[warp][lane]      = x[row * HH + lane];
    xs[warp][lane + 32] = x[row * HH + lane + 32];
    __syncwarp();

    float a0 = b1[lane];
    float a1 = b1[lane + 32];
#pragma unroll
    for (int k = 0; k < HH; k++) {
        float xv = xs[warp][k];
        a0 = fmaf(xv, Ws[k * HH + lane],      a0);
        a1 = fmaf(xv, Ws[k * HH + lane + 32], a1);
    }
    g_h[row * HH + lane]      = fmaxf(a0, 0.f);
    g_h[row * HH + lane + 32] = fmaxf(a1, 0.f);
}

// ---------------------------------------------------------------------------
// Edge scatter: lap[dst] += w * h[src],  w = -dis[src]*dis[dst]
// 16 threads per edge, each handles 4 features, vec4 red.global
// ---------------------------------------------------------------------------
__global__ __launch_bounds__(256) void k_scatter(const int* __restrict__ ei) {
    unsigned tid = blockIdx.x * 256u + threadIdx.x;
    unsigned e = tid >> 4;
    if (e >= EE) return;
    int f = (int)(tid & 15u) << 2;

    int st = g_stride;
    int s = __ldg(&ei[e * st]);
    int d = __ldg(&ei[(EE + e) * st]);
    float w = -__ldg(&g_dis[s]) * __ldg(&g_dis[d]);

    float4 hv = *(const float4*)&g_h[s * HH + f];
    float* p = &g_lap[d * HH + f];
    asm volatile("red.global.add.v4.f32 [%0], {%1,%2,%3,%4};"
                 :: "l"(p), "f"(w * hv.x), "f"(w * hv.y),
                    "f"(w * hv.z), "f"(w * hv.w)
                 : "memory");
}

// ---------------------------------------------------------------------------
// Fused: h2 = relu(h@W20 + lap@W21 + b2); o = (h2+h)@Wl + bl; log_softmax
// ---------------------------------------------------------------------------
__global__ __launch_bounds__(256) void k_final(const float* __restrict__ W20,
                                               const float* __restrict__ W21,
                                               const float* __restrict__ b2,
                                               const float* __restrict__ Wl,
                                               const float* __restrict__ bl,
                                               float* __restrict__ out) {
    __shared__ float W20s[HH * HH];
    __shared__ float W21s[HH * HH];
    __shared__ float Wls[HH * CC];
    __shared__ float hs[8][HH];
    __shared__ float ls[8][HH];

    for (int i = threadIdx.x; i < HH * HH; i += 256) {
        W20s[i] = W20[i];
        W21s[i] = W21[i];
    }
    for (int i = threadIdx.x; i < HH * CC; i += 256) Wls[i] = Wl[i];
    __syncthreads();

    int warp = threadIdx.x >> 5;
    int lane = threadIdx.x & 31;
    int row = blockIdx.x * 8 + warp;
    if (row >= NN) return;

    hs[warp][lane]      = g_h[row * HH + lane];
    hs[warp][lane + 32] = g_h[row * HH + lane + 32];
    ls[warp][lane]      = g_lap[row * HH + lane];
    ls[warp][lane + 32] = g_lap[row * HH + lane + 32];
    __syncwarp();

    float a0 = b2[lane];
    float a1 = b2[lane + 32];
#pragma unroll
    for (int k = 0; k < HH; k++) {
        float hv = hs[warp][k];
        float lv = ls[warp][k];
        a0 = fmaf(hv, W20s[k * HH + lane],      a0);
        a0 = fmaf(lv, W21s[k * HH + lane],      a0);
        a1 = fmaf(hv, W20s[k * HH + lane + 32], a1);
        a1 = fmaf(lv, W21s[k * HH + lane + 32], a1);
    }
    float s0 = fmaxf(a0, 0.f) + hs[warp][lane];
    float s1 = fmaxf(a1, 0.f) + hs[warp][lane + 32];

    float p[CC];
#pragma unroll
    for (int c = 0; c < CC; c++)
        p[c] = fmaf(s0, Wls[lane * CC + c], s1 * Wls[(lane + 32) * CC + c]);

#pragma unroll
    for (int off = 16; off > 0; off >>= 1) {
#pragma unroll
        for (int c = 0; c < CC; c++)
            p[c] += __shfl_xor_sync(0xffffffffu, p[c], off);
    }

    if (lane == 0) {
        float m = -1e30f;
#pragma unroll
        for (int c = 0; c < CC; c++) {
            p[c] += bl[c];
            m = fmaxf(m, p[c]);
        }
        float sum = 0.f;
#pragma unroll
        for (int c = 0; c < CC; c++) sum += expf(p[c] - m);
        float lse = logf(sum);
#pragma unroll
        for (int c = 0; c < CC; c++) out[row * CC + c] = p[c] - m - lse;
    }
}

// ---------------------------------------------------------------------------
extern "C" void kernel_launch(void* const* d_in, const int* in_sizes, int n_in,
                              void* d_out, int out_size) {
    const float* x   = (const float*)d_in[0];
    const int*   ei  = (const int*)d_in[1];
    const float* W1  = (const float*)d_in[2];
    const float* b1  = (const float*)d_in[3];
    const float* W20 = (const float*)d_in[4];
    const float* W21 = (const float*)d_in[5];
    const float* b2  = (const float*)d_in[6];
    const float* Wl  = (const float*)d_in[7];
    const float* bl  = (const float*)d_in[8];
    float* out = (float*)d_out;

    k_detect<<<1, 1>>>(ei);
    k_zero<<<2048, 256>>>();
    k_deg<<<(EE + 255) / 256, 256>>>(ei);
    k_dis<<<(NN + 255) / 256, 256>>>();
    k_gemm1<<<(NN + 7) / 8, 256>>>(x, W1, b1);
    k_scatter<<<(EE * 16 + 255) / 256, 256>>>(ei);
    k_final<<<(NN + 7) / 8, 256>>>(W20, W21, b2, Wl, bl, out);
}